// round 9
// baseline (speedup 1.0000x reference)
// FastQuantizedLinear on GB300 (sm_103a host, compute_103 generic PTX target)
// out[8192,4096] = x[8192,4096] @ ((W_int8 - zp) * s)^T + bias
// Single-pass fp16 HMMA (W exact in fp16, x rounded: rel_err ~2e-4 < 1e-3).
// R9: R7 (2 CTAs/SM, 128x128 tile, 3 stages) + DEFERRED stage release: the
// __syncthreads + producer reissue for stage s-1 happen at the TOP of the next
// iteration, after the prior iteration's MMAs consumed all its fragments
// (MMA issue guarantees LDSM completion -> no read/overwrite race, unlike R8).
#include <cuda_runtime.h>
#include <cuda_fp16.h>
#include <cstdint>

// ---------------- problem constants ----------------
#define DIM_M 8192   // B*S
#define DIM_N 4096   // OUT
#define DIM_K 4096   // IN

#define BM 128
#define BN 128
#define BK 64             // fp16 elems per k-chunk (128 bytes/row, SW128)
#define KT (DIM_K / BK)   // 64 k-iterations
#define MT (DIM_M / BM)   // 64 m-tiles
#define NT (DIM_N / BN)   // 32 n-tiles

#define A_TILE_BYTES  (BM * 128)          // 16384
#define W_TILE_BYTES  (BN * 128)          // 16384
#define STAGE_BYTES   (A_TILE_BYTES + W_TILE_BYTES)      // 32768
#define NSTAGES 3
#define SMEM_DYN (1024 + NSTAGES * STAGE_BYTES)          // 99328 (x2 CTAs = 198.7KB/SM)

#define OFF_FULL(s)  ((s) * 8)
#define STAGE_BASE(s) (1024 + (s) * STAGE_BYTES)
#define ST_A 0
#define ST_W A_TILE_BYTES

// ---------------- scratch (device globals; allocation-free rule) ------------
__device__ __align__(1024) unsigned char g_A [(unsigned long long)MT * KT * A_TILE_BYTES];   // 64 MB
__device__ __align__(1024) unsigned char g_Wt[(unsigned long long)NT * KT * W_TILE_BYTES];   // 32 MB
__device__ float g_rowsum[DIM_M];

// ---------------- PTX helpers (generic-target safe) ----------------
__device__ __forceinline__ uint32_t smem_u32(const void* p) {
    uint32_t a;
    asm("{ .reg .u64 t; cvta.to.shared.u64 t, %1; cvt.u32.u64 %0, t; }" : "=r"(a) : "l"(p));
    return a;
}
__device__ __forceinline__ uint32_t swz128(uint32_t o) { return o ^ ((o >> 3) & 0x70); }

#define MBAR_INIT(addr, cnt) \
    asm volatile("mbarrier.init.shared.b64 [%0], %1;" :: "r"(addr), "r"(cnt) : "memory")
#define MBAR_EXPECT_TX(addr, bytes) \
    asm volatile("mbarrier.arrive.expect_tx.shared.b64 _, [%0], %1;" :: "r"(addr), "r"(bytes) : "memory")
#define MBAR_WAIT(addr, parity) do {                                                  \
    uint32_t _m = (addr); uint32_t _p = (parity); uint32_t _d;                        \
    asm volatile("{\n\t.reg .pred p;\n\t"                                             \
        "mbarrier.try_wait.parity.acquire.cta.shared::cta.b64 p, [%1], %2;\n\t"       \
        "selp.b32 %0, 1, 0, p;\n\t}"                                                  \
        : "=r"(_d) : "r"(_m), "r"(_p) : "memory");                                    \
    if (!_d) {                                                                        \
        asm volatile("{\n\t.reg .pred P1;\n\t"                                        \
            "WL_%=:\n\t"                                                              \
            "mbarrier.try_wait.parity.acquire.cta.shared::cta.b64 P1, [%0], %1, 0x989680;\n\t" \
            "@P1 bra.uni WD_%=;\n\t"                                                  \
            "bra.uni WL_%=;\n\t"                                                      \
            "WD_%=:\n\t}" :: "r"(_m), "r"(_p) : "memory");                            \
    }                                                                                 \
} while (0)

__device__ __forceinline__ void bulk_g2s(uint32_t dst, const void* src, uint32_t bytes, uint32_t mbar) {
    asm volatile(
        "cp.async.bulk.shared::cluster.global.mbarrier::complete_tx::bytes [%0], [%1], %2, [%3];"
        :: "r"(dst), "l"(src), "r"(bytes), "r"(mbar) : "memory");
}

__device__ __forceinline__ void ldsm4(uint32_t* r, uint32_t addr) {
    asm volatile("ldmatrix.sync.aligned.m8n8.x4.shared.b16 {%0,%1,%2,%3}, [%4];"
        : "=r"(r[0]), "=r"(r[1]), "=r"(r[2]), "=r"(r[3]) : "r"(addr));
}

__device__ __forceinline__ void mma_fp16(float* c, const uint32_t* a, uint32_t b0, uint32_t b1) {
    asm volatile(
        "mma.sync.aligned.m16n8k16.row.col.f32.f16.f16.f32 "
        "{%0,%1,%2,%3}, {%4,%5,%6,%7}, {%8,%9}, {%0,%1,%2,%3};"
        : "+f"(c[0]), "+f"(c[1]), "+f"(c[2]), "+f"(c[3])
        : "r"(a[0]), "r"(a[1]), "r"(a[2]), "r"(a[3]), "r"(b0), "r"(b1));
}

// ---------------- prolog: convert W int32 -> fp16 (exact), tiled + swizzled --
// Tile layout: g_Wt[ntile][kt][128 rows (n) x 64 fp16 (k), SW128-swizzled rows]
__global__ void __launch_bounds__(512) k_convert_w(const int* __restrict__ w) {
    int n = blockIdx.x;        // 0..4095
    int t = threadIdx.x;       // 0..511, handles 8 consecutive k
    const int4* row = reinterpret_cast<const int4*>(w + (size_t)n * DIM_K);
    int4 a = row[2 * t], b = row[2 * t + 1];
    int v[8] = {a.x, a.y, a.z, a.w, b.x, b.y, b.z, b.w};
    union { __half h[8]; uint4 u; } q;
#pragma unroll
    for (int i = 0; i < 8; i++) q.h[i] = __float2half_rn((float)v[i]);   // exact for int8 range
    int k0 = t * 8;
    int kt = k0 >> 6, c = k0 & 63;
    int ntile = n >> 7, r = n & 127;
    size_t tile = ((size_t)(ntile * KT + kt)) << 14;        // * 16384
    uint32_t off = swz128((uint32_t)(r * 128 + c * 2));
    *reinterpret_cast<uint4*>(g_Wt + tile + off) = q.u;
}

// ---------------- prolog: convert A fp32 -> fp16 + rowsums -------------------
__global__ void __launch_bounds__(512) k_convert_a(const float* __restrict__ x) {
    int m = blockIdx.x;        // 0..8191
    int t = threadIdx.x;
    const float4* row = reinterpret_cast<const float4*>(x + (size_t)m * DIM_K);
    float4 f0 = row[2 * t], f1 = row[2 * t + 1];
    float v[8] = {f0.x, f0.y, f0.z, f0.w, f1.x, f1.y, f1.z, f1.w};
    union { __half h[8]; uint4 u; } q;
    float s = 0.f;
#pragma unroll
    for (int i = 0; i < 8; i++) {
        s += v[i];
        q.h[i] = __float2half_rn(v[i]);
    }
    int k0 = t * 8;
    int kt = k0 >> 6, c = k0 & 63;
    int mt = m >> 7, r = m & 127;
    size_t tile = ((size_t)(mt * KT + kt)) << 14;            // * 16384
    uint32_t off = swz128((uint32_t)(r * 128 + c * 2));
    *reinterpret_cast<uint4*>(g_A + tile + off) = q.u;

    // block-reduce row sum (for zero_point correction)
#pragma unroll
    for (int o = 16; o > 0; o >>= 1) s += __shfl_down_sync(0xFFFFFFFFu, s, o);
    __shared__ float sred[16];
    if ((t & 31) == 0) sred[t >> 5] = s;
    __syncthreads();
    if (t == 0) {
        float tot = 0.f;
#pragma unroll
        for (int i = 0; i < 16; i++) tot += sred[i];
        g_rowsum[m] = tot;
    }
}

// -------- main GEMM: fp16 mma.sync, CTA 128x128, warp 64x64, 2 CTAs/SM -------
__global__ void __launch_bounds__(128, 2)
k_gemm(const float* __restrict__ scale, const float* __restrict__ zp,
       const float* __restrict__ bias, float* __restrict__ out) {
    extern __shared__ unsigned char smem[];
    const uint32_t sb = smem_u32(smem);
    const int tid  = threadIdx.x;
    const int wid  = tid >> 5;
    const int lane = tid & 31;
    const int ntile = blockIdx.x;     // 0..31
    const int mtile = blockIdx.y;     // 0..63

    const int warpM = wid >> 1;       // 0..1 -> m offset warpM*64
    const int warpN = wid & 1;        // 0..1 -> n offset warpN*64

    if (tid == 0) {
#pragma unroll
        for (int s = 0; s < NSTAGES; ++s) MBAR_INIT(sb + OFF_FULL(s), 1);
    }
    __syncthreads();

    const unsigned char* gA = g_A  + ((size_t)mtile * KT) * A_TILE_BYTES;
    const unsigned char* gW = g_Wt + ((size_t)ntile * KT) * W_TILE_BYTES;

    // prefill all stages
    if (tid == 0) {
#pragma unroll
        for (int it = 0; it < NSTAGES; ++it) {
            uint32_t full = sb + OFF_FULL(it);
            MBAR_EXPECT_TX(full, STAGE_BYTES);
            uint32_t base = sb + STAGE_BASE(it);
            bulk_g2s(base + ST_A, gA + (size_t)it * A_TILE_BYTES, A_TILE_BYTES, full);
            bulk_g2s(base + ST_W, gW + (size_t)it * W_TILE_BYTES, W_TILE_BYTES, full);
        }
    }

    float acc[4][8][4];               // [mf 16-row][n8 block][frag]
#pragma unroll
    for (int i = 0; i < 4; ++i)
#pragma unroll
        for (int j = 0; j < 8; ++j)
#pragma unroll
            for (int q = 0; q < 4; ++q) acc[i][j][q] = 0.f;

    // Hoisted swizzle math: swz128(r*128 + c2) = r*128 + (c2 ^ ((r&7)<<4)).
    const int lr = lane & 15;              // ldmatrix row
    const int lc = (lane >> 4) << 3;       // 0 or 8 (k offset within 16)
    uint32_t aRow[4], aKey[4], wRow[4], wKey[4];
#pragma unroll
    for (int mf = 0; mf < 4; ++mf) {
        int r = warpM * 64 + mf * 16 + lr;
        aRow[mf] = (uint32_t)(r * 128);
        aKey[mf] = (uint32_t)((r & 7) << 4);
    }
#pragma unroll
    for (int nf = 0; nf < 4; ++nf) {
        int r = warpN * 64 + nf * 16 + lr;
        wRow[nf] = (uint32_t)(r * 128);
        wKey[nf] = (uint32_t)((r & 7) << 4);
    }

    uint32_t af[2][4][4], bw[2][4][4];   // double-buffered fragments

#define LOAD_FRAGS(b, aB, wB, kc)                                              \
    do {                                                                       \
        uint32_t c2 = (uint32_t)(((kc) + lc) * 2);                             \
        _Pragma("unroll")                                                      \
        for (int mf = 0; mf < 4; ++mf)                                         \
            ldsm4(af[b][mf], (aB) + aRow[mf] + (c2 ^ aKey[mf]));               \
        _Pragma("unroll")                                                      \
        for (int nf = 0; nf < 4; ++nf)                                         \
            ldsm4(bw[b][nf], (wB) + wRow[nf] + (c2 ^ wKey[nf]));               \
    } while (0)

#define DO_MMAS(b)                                                             \
    do {                                                                       \
        _Pragma("unroll")                                                      \
        for (int mf = 0; mf < 4; ++mf) {                                       \
            _Pragma("unroll")                                                  \
            for (int nf = 0; nf < 4; ++nf) {                                   \
                mma_fp16(acc[mf][2 * nf + 0], af[b][mf], bw[b][nf][0], bw[b][nf][2]); \
                mma_fp16(acc[mf][2 * nf + 1], af[b][mf], bw[b][nf][1], bw[b][nf][3]); \
            }                                                                  \
        }                                                                      \
    } while (0)

    int s = 0, ph = 0;
    for (int it = 0; it < KT; ++it) {
        MBAR_WAIT(sb + OFF_FULL(s), ph);
        const uint32_t base = sb + STAGE_BASE(s);
        const uint32_t aB = base + ST_A;
        const uint32_t wB = base + ST_W;

        // Start consuming the current stage first...
        LOAD_FRAGS(0, aB, wB, 0);
        LOAD_FRAGS(1, aB, wB, 16);

        // ...then release stage s-1. Every warp's stage-(s-1) fragments were
        // consumed by MMAs issued LAST iteration (MMA issue requires the LDSM
        // results, so those smem reads are fully complete), making the
        // overwrite race-free — unlike R8's early release of the CURRENT stage.
        // Barrier drain + copy issue hide under this iteration's MMA blocks.
        if (it > 0) {
            __syncthreads();
            if (tid == 0 && (it - 1) + NSTAGES < KT) {
                const int ps  = (s + NSTAGES - 1) % NSTAGES;   // stage of it-1
                const int nit = (it - 1) + NSTAGES;
                uint32_t full = sb + OFF_FULL(ps);
                MBAR_EXPECT_TX(full, STAGE_BYTES);
                uint32_t nb = sb + STAGE_BASE(ps);
                bulk_g2s(nb + ST_A, gA + (size_t)nit * A_TILE_BYTES, A_TILE_BYTES, full);
                bulk_g2s(nb + ST_W, gW + (size_t)nit * W_TILE_BYTES, W_TILE_BYTES, full);
            }
        }

        DO_MMAS(0);
        LOAD_FRAGS(0, aB, wB, 32);
        DO_MMAS(1);
        LOAD_FRAGS(1, aB, wB, 48);
        DO_MMAS(0);
        DO_MMAS(1);

        if (++s == NSTAGES) { s = 0; ph ^= 1; }
    }

    // -------- epilogue: registers -> gmem (sector-complete float2 stores) ----
    const int tq = lane >> 2;   // 0..7 row within 8
    const int tr = lane & 3;    // col pair
    const int m_base = mtile * BM + warpM * 64;
    const int n_base = ntile * BN + warpN * 64;

#pragma unroll
    for (int mf = 0; mf < 4; ++mf) {
        int r0 = m_base + mf * 16 + tq;
        int r1 = r0 + 8;
        float rs0 = g_rowsum[r0];
        float rs1 = g_rowsum[r1];
        float* o0 = out + (size_t)r0 * DIM_N;
        float* o1 = out + (size_t)r1 * DIM_N;
#pragma unroll
        for (int j = 0; j < 8; ++j) {
            int n = n_base + j * 8 + 2 * tr;
            float2 sc = *reinterpret_cast<const float2*>(scale + n);
            float2 zq = *reinterpret_cast<const float2*>(zp + n);
            float2 bb = *reinterpret_cast<const float2*>(bias + n);
            float* c = acc[mf][j];
            float2 v0, v1;
            v0.x = c[0] * sc.x + bb.x - sc.x * zq.x * rs0;
            v0.y = c[1] * sc.y + bb.y - sc.y * zq.y * rs0;
            v1.x = c[2] * sc.x + bb.x - sc.x * zq.x * rs1;
            v1.y = c[3] * sc.y + bb.y - sc.y * zq.y * rs1;
            *reinterpret_cast<float2*>(o0 + n) = v0;
            *reinterpret_cast<float2*>(o1 + n) = v1;
        }
    }
}

// ---------------- launch ----------------
extern "C" void kernel_launch(void* const* d_in, const int* in_sizes, int n_in,
                              void* d_out, int out_size) {
    const float* input  = (const float*)d_in[0];   // [4,2048,4096] fp32
    const int*   w_int  = (const int*)  d_in[1];   // [4096,4096] int32
    const float* scale  = (const float*)d_in[2];   // [4096,1]
    const float* zp     = (const float*)d_in[3];   // [4096,1]
    const float* bias   = (const float*)d_in[4];   // [4096]
    float* out = (float*)d_out;

    k_convert_w<<<DIM_N, 512>>>(w_int);
    k_convert_a<<<DIM_M, 512>>>(input);

    cudaFuncSetAttribute(k_gemm, cudaFuncAttributeMaxDynamicSharedMemorySize, SMEM_DYN);

    dim3 grid(NT, MT);   // x = n-tile fastest: co-resident CTAs share A tiles in L2
    k_gemm<<<grid, 128, SMEM_DYN>>>(scale, zp, bias, out);
}

// round 10
// speedup vs baseline: 1.0472x; 1.0472x over previous
// FastQuantizedLinear on GB300 (sm_103a host, compute_103 generic PTX target)
// out[8192,4096] = x[8192,4096] @ ((W_int8 - zp) * s)^T + bias
// Single-pass fp16 HMMA (W exact in fp16, x rounded: rel_err ~2e-4 < 1e-3).
// R10: GEMM reverted to R7 verbatim (best: 688.9us; R8/R9 barrier experiments
// both lost). Prologs fused into one kernel (block-uniform branch) to merge
// their HBM streams and kill one launch boundary + tail.
#include <cuda_runtime.h>
#include <cuda_fp16.h>
#include <cstdint>

// ---------------- problem constants ----------------
#define DIM_M 8192   // B*S
#define DIM_N 4096   // OUT
#define DIM_K 4096   // IN

#define BM 128
#define BN 128
#define BK 64             // fp16 elems per k-chunk (128 bytes/row, SW128)
#define KT (DIM_K / BK)   // 64 k-iterations
#define MT (DIM_M / BM)   // 64 m-tiles
#define NT (DIM_N / BN)   // 32 n-tiles

#define A_TILE_BYTES  (BM * 128)          // 16384
#define W_TILE_BYTES  (BN * 128)          // 16384
#define STAGE_BYTES   (A_TILE_BYTES + W_TILE_BYTES)      // 32768
#define NSTAGES 3
#define SMEM_DYN (1024 + NSTAGES * STAGE_BYTES)          // 99328 (x2 CTAs = 198.7KB/SM)

#define OFF_FULL(s)  ((s) * 8)
#define STAGE_BASE(s) (1024 + (s) * STAGE_BYTES)
#define ST_A 0
#define ST_W A_TILE_BYTES

// ---------------- scratch (device globals; allocation-free rule) ------------
__device__ __align__(1024) unsigned char g_A [(unsigned long long)MT * KT * A_TILE_BYTES];   // 64 MB
__device__ __align__(1024) unsigned char g_Wt[(unsigned long long)NT * KT * W_TILE_BYTES];   // 32 MB
__device__ float g_rowsum[DIM_M];

// ---------------- PTX helpers (generic-target safe) ----------------
__device__ __forceinline__ uint32_t smem_u32(const void* p) {
    uint32_t a;
    asm("{ .reg .u64 t; cvta.to.shared.u64 t, %1; cvt.u32.u64 %0, t; }" : "=r"(a) : "l"(p));
    return a;
}
__device__ __forceinline__ uint32_t swz128(uint32_t o) { return o ^ ((o >> 3) & 0x70); }

#define MBAR_INIT(addr, cnt) \
    asm volatile("mbarrier.init.shared.b64 [%0], %1;" :: "r"(addr), "r"(cnt) : "memory")
#define MBAR_EXPECT_TX(addr, bytes) \
    asm volatile("mbarrier.arrive.expect_tx.shared.b64 _, [%0], %1;" :: "r"(addr), "r"(bytes) : "memory")
#define MBAR_WAIT(addr, parity) do {                                                  \
    uint32_t _m = (addr); uint32_t _p = (parity); uint32_t _d;                        \
    asm volatile("{\n\t.reg .pred p;\n\t"                                             \
        "mbarrier.try_wait.parity.acquire.cta.shared::cta.b64 p, [%1], %2;\n\t"       \
        "selp.b32 %0, 1, 0, p;\n\t}"                                                  \
        : "=r"(_d) : "r"(_m), "r"(_p) : "memory");                                    \
    if (!_d) {                                                                        \
        asm volatile("{\n\t.reg .pred P1;\n\t"                                        \
            "WL_%=:\n\t"                                                              \
            "mbarrier.try_wait.parity.acquire.cta.shared::cta.b64 P1, [%0], %1, 0x989680;\n\t" \
            "@P1 bra.uni WD_%=;\n\t"                                                  \
            "bra.uni WL_%=;\n\t"                                                      \
            "WD_%=:\n\t}" :: "r"(_m), "r"(_p) : "memory");                            \
    }                                                                                 \
} while (0)

__device__ __forceinline__ void bulk_g2s(uint32_t dst, const void* src, uint32_t bytes, uint32_t mbar) {
    asm volatile(
        "cp.async.bulk.shared::cluster.global.mbarrier::complete_tx::bytes [%0], [%1], %2, [%3];"
        :: "r"(dst), "l"(src), "r"(bytes), "r"(mbar) : "memory");
}

__device__ __forceinline__ void ldsm4(uint32_t* r, uint32_t addr) {
    asm volatile("ldmatrix.sync.aligned.m8n8.x4.shared.b16 {%0,%1,%2,%3}, [%4];"
        : "=r"(r[0]), "=r"(r[1]), "=r"(r[2]), "=r"(r[3]) : "r"(addr));
}

__device__ __forceinline__ void mma_fp16(float* c, const uint32_t* a, uint32_t b0, uint32_t b1) {
    asm volatile(
        "mma.sync.aligned.m16n8k16.row.col.f32.f16.f16.f32 "
        "{%0,%1,%2,%3}, {%4,%5,%6,%7}, {%8,%9}, {%0,%1,%2,%3};"
        : "+f"(c[0]), "+f"(c[1]), "+f"(c[2]), "+f"(c[3])
        : "r"(a[0]), "r"(a[1]), "r"(a[2]), "r"(a[3]), "r"(b0), "r"(b1));
}

// ------------- fused prolog: W int32->fp16 tiles | A fp32->fp16 tiles+rowsums
// Blocks [0, DIM_N)          : one W row each  (exact int8-in-fp16)
// Blocks [DIM_N, DIM_N+DIM_M): one A row each  (fp16 round + fp32 rowsum)
__global__ void __launch_bounds__(512) k_convert(const int* __restrict__ w,
                                                 const float* __restrict__ x) {
    int bid = blockIdx.x;
    int t = threadIdx.x;       // 0..511, handles 8 consecutive k
    if (bid < DIM_N) {
        int n = bid;
        const int4* row = reinterpret_cast<const int4*>(w + (size_t)n * DIM_K);
        int4 a = row[2 * t], b = row[2 * t + 1];
        int v[8] = {a.x, a.y, a.z, a.w, b.x, b.y, b.z, b.w};
        union { __half h[8]; uint4 u; } q;
#pragma unroll
        for (int i = 0; i < 8; i++) q.h[i] = __float2half_rn((float)v[i]);   // exact for int8 range
        int k0 = t * 8;
        int kt = k0 >> 6, c = k0 & 63;
        int ntile = n >> 7, r = n & 127;
        size_t tile = ((size_t)(ntile * KT + kt)) << 14;        // * 16384
        uint32_t off = swz128((uint32_t)(r * 128 + c * 2));
        *reinterpret_cast<uint4*>(g_Wt + tile + off) = q.u;
    } else {
        int m = bid - DIM_N;
        const float4* row = reinterpret_cast<const float4*>(x + (size_t)m * DIM_K);
        float4 f0 = row[2 * t], f1 = row[2 * t + 1];
        float v[8] = {f0.x, f0.y, f0.z, f0.w, f1.x, f1.y, f1.z, f1.w};
        union { __half h[8]; uint4 u; } q;
        float s = 0.f;
#pragma unroll
        for (int i = 0; i < 8; i++) {
            s += v[i];
            q.h[i] = __float2half_rn(v[i]);
        }
        int k0 = t * 8;
        int kt = k0 >> 6, c = k0 & 63;
        int mt = m >> 7, r = m & 127;
        size_t tile = ((size_t)(mt * KT + kt)) << 14;            // * 16384
        uint32_t off = swz128((uint32_t)(r * 128 + c * 2));
        *reinterpret_cast<uint4*>(g_A + tile + off) = q.u;

        // block-reduce row sum (for zero_point correction)
#pragma unroll
        for (int o = 16; o > 0; o >>= 1) s += __shfl_down_sync(0xFFFFFFFFu, s, o);
        __shared__ float sred[16];
        if ((t & 31) == 0) sred[t >> 5] = s;
        __syncthreads();
        if (t == 0) {
            float tot = 0.f;
#pragma unroll
            for (int i = 0; i < 16; i++) tot += sred[i];
            g_rowsum[m] = tot;
        }
    }
}

// -------- main GEMM: fp16 mma.sync, CTA 128x128, warp 64x64, 2 CTAs/SM -------
// (R7 verbatim — best measured configuration.)
__global__ void __launch_bounds__(128, 2)
k_gemm(const float* __restrict__ scale, const float* __restrict__ zp,
       const float* __restrict__ bias, float* __restrict__ out) {
    extern __shared__ unsigned char smem[];
    const uint32_t sb = smem_u32(smem);
    const int tid  = threadIdx.x;
    const int wid  = tid >> 5;
    const int lane = tid & 31;
    const int ntile = blockIdx.x;     // 0..31
    const int mtile = blockIdx.y;     // 0..63

    const int warpM = wid >> 1;       // 0..1 -> m offset warpM*64
    const int warpN = wid & 1;        // 0..1 -> n offset warpN*64

    if (tid == 0) {
#pragma unroll
        for (int s = 0; s < NSTAGES; ++s) MBAR_INIT(sb + OFF_FULL(s), 1);
    }
    __syncthreads();

    const unsigned char* gA = g_A  + ((size_t)mtile * KT) * A_TILE_BYTES;
    const unsigned char* gW = g_Wt + ((size_t)ntile * KT) * W_TILE_BYTES;

    // prefill all stages
    if (tid == 0) {
#pragma unroll
        for (int it = 0; it < NSTAGES; ++it) {
            uint32_t full = sb + OFF_FULL(it);
            MBAR_EXPECT_TX(full, STAGE_BYTES);
            uint32_t base = sb + STAGE_BASE(it);
            bulk_g2s(base + ST_A, gA + (size_t)it * A_TILE_BYTES, A_TILE_BYTES, full);
            bulk_g2s(base + ST_W, gW + (size_t)it * W_TILE_BYTES, W_TILE_BYTES, full);
        }
    }

    float acc[4][8][4];               // [mf 16-row][n8 block][frag]
#pragma unroll
    for (int i = 0; i < 4; ++i)
#pragma unroll
        for (int j = 0; j < 8; ++j)
#pragma unroll
            for (int q = 0; q < 4; ++q) acc[i][j][q] = 0.f;

    // Hoisted swizzle math: swz128(r*128 + c2) = r*128 + (c2 ^ ((r&7)<<4)).
    const int lr = lane & 15;              // ldmatrix row
    const int lc = (lane >> 4) << 3;       // 0 or 8 (k offset within 16)
    uint32_t aRow[4], aKey[4], wRow[4], wKey[4];
#pragma unroll
    for (int mf = 0; mf < 4; ++mf) {
        int r = warpM * 64 + mf * 16 + lr;
        aRow[mf] = (uint32_t)(r * 128);
        aKey[mf] = (uint32_t)((r & 7) << 4);
    }
#pragma unroll
    for (int nf = 0; nf < 4; ++nf) {
        int r = warpN * 64 + nf * 16 + lr;
        wRow[nf] = (uint32_t)(r * 128);
        wKey[nf] = (uint32_t)((r & 7) << 4);
    }

    uint32_t af[2][4][4], bw[2][4][4];   // double-buffered fragments

#define LOAD_FRAGS(b, aB, wB, kc)                                              \
    do {                                                                       \
        uint32_t c2 = (uint32_t)(((kc) + lc) * 2);                             \
        _Pragma("unroll")                                                      \
        for (int mf = 0; mf < 4; ++mf)                                         \
            ldsm4(af[b][mf], (aB) + aRow[mf] + (c2 ^ aKey[mf]));               \
        _Pragma("unroll")                                                      \
        for (int nf = 0; nf < 4; ++nf)                                         \
            ldsm4(bw[b][nf], (wB) + wRow[nf] + (c2 ^ wKey[nf]));               \
    } while (0)

#define DO_MMAS(b)                                                             \
    do {                                                                       \
        _Pragma("unroll")                                                      \
        for (int mf = 0; mf < 4; ++mf) {                                       \
            _Pragma("unroll")                                                  \
            for (int nf = 0; nf < 4; ++nf) {                                   \
                mma_fp16(acc[mf][2 * nf + 0], af[b][mf], bw[b][nf][0], bw[b][nf][2]); \
                mma_fp16(acc[mf][2 * nf + 1], af[b][mf], bw[b][nf][1], bw[b][nf][3]); \
            }                                                                  \
        }                                                                      \
    } while (0)

    int s = 0, ph = 0;
    for (int it = 0; it < KT; ++it) {
        MBAR_WAIT(sb + OFF_FULL(s), ph);
        const uint32_t base = sb + STAGE_BASE(s);
        const uint32_t aB = base + ST_A;
        const uint32_t wB = base + ST_W;

        LOAD_FRAGS(0, aB, wB, 0);
        LOAD_FRAGS(1, aB, wB, 16);
        DO_MMAS(0);
        LOAD_FRAGS(0, aB, wB, 32);
        DO_MMAS(1);
        LOAD_FRAGS(1, aB, wB, 48);
        DO_MMAS(0);
        DO_MMAS(1);

        __syncthreads();                   // all warps done reading stage s
        if (tid == 0 && it + NSTAGES < KT) {
            int nit = it + NSTAGES;
            uint32_t full = sb + OFF_FULL(s);
            MBAR_EXPECT_TX(full, STAGE_BYTES);
            uint32_t nb = sb + STAGE_BASE(s);
            bulk_g2s(nb + ST_A, gA + (size_t)nit * A_TILE_BYTES, A_TILE_BYTES, full);
            bulk_g2s(nb + ST_W, gW + (size_t)nit * W_TILE_BYTES, W_TILE_BYTES, full);
        }
        if (++s == NSTAGES) { s = 0; ph ^= 1; }
    }

    // -------- epilogue: registers -> gmem (sector-complete float2 stores) ----
    const int tq = lane >> 2;   // 0..7 row within 8
    const int tr = lane & 3;    // col pair
    const int m_base = mtile * BM + warpM * 64;
    const int n_base = ntile * BN + warpN * 64;

#pragma unroll
    for (int mf = 0; mf < 4; ++mf) {
        int r0 = m_base + mf * 16 + tq;
        int r1 = r0 + 8;
        float rs0 = g_rowsum[r0];
        float rs1 = g_rowsum[r1];
        float* o0 = out + (size_t)r0 * DIM_N;
        float* o1 = out + (size_t)r1 * DIM_N;
#pragma unroll
        for (int j = 0; j < 8; ++j) {
            int n = n_base + j * 8 + 2 * tr;
            float2 sc = *reinterpret_cast<const float2*>(scale + n);
            float2 zq = *reinterpret_cast<const float2*>(zp + n);
            float2 bb = *reinterpret_cast<const float2*>(bias + n);
            float* c = acc[mf][j];
            float2 v0, v1;
            v0.x = c[0] * sc.x + bb.x - sc.x * zq.x * rs0;
            v0.y = c[1] * sc.y + bb.y - sc.y * zq.y * rs0;
            v1.x = c[2] * sc.x + bb.x - sc.x * zq.x * rs1;
            v1.y = c[3] * sc.y + bb.y - sc.y * zq.y * rs1;
            *reinterpret_cast<float2*>(o0 + n) = v0;
            *reinterpret_cast<float2*>(o1 + n) = v1;
        }
    }
}

// ---------------- launch ----------------
extern "C" void kernel_launch(void* const* d_in, const int* in_sizes, int n_in,
                              void* d_out, int out_size) {
    const float* input  = (const float*)d_in[0];   // [4,2048,4096] fp32
    const int*   w_int  = (const int*)  d_in[1];   // [4096,4096] int32
    const float* scale  = (const float*)d_in[2];   // [4096,1]
    const float* zp     = (const float*)d_in[3];   // [4096,1]
    const float* bias   = (const float*)d_in[4];   // [4096]
    float* out = (float*)d_out;

    k_convert<<<DIM_N + DIM_M, 512>>>(w_int, input);

    cudaFuncSetAttribute(k_gemm, cudaFuncAttributeMaxDynamicSharedMemorySize, SMEM_DYN);

    dim3 grid(NT, MT);   // x = n-tile fastest: co-resident CTAs share A tiles in L2
    k_gemm<<<grid, 128, SMEM_DYN>>>(scale, zp, bias, out);
}

// round 11
// speedup vs baseline: 1.0682x; 1.0201x over previous
// FastQuantizedLinear on GB300 (sm_103a host, compute_103 generic PTX target)
// out[8192,4096] = x[8192,4096] @ ((W_int8 - zp) * s)^T + bias
// Single-pass fp16 HMMA (W exact in fp16, x rounded: rel_err ~2e-4 < 1e-3).
// R11: ncu showed tensor=70.3%, DRAM 4%, L1 38%, occ 12.1% (2 warps/SMSP) ->
// HMMA starves on latency, not bandwidth. Split each 128x128 CTA into 8 warps
// (warp tile 32x64, single-buffered frags) -> 4 warps/SMSP for latency hiding.
#include <cuda_runtime.h>
#include <cuda_fp16.h>
#include <cstdint>

// ---------------- problem constants ----------------
#define DIM_M 8192   // B*S
#define DIM_N 4096   // OUT
#define DIM_K 4096   // IN

#define BM 128
#define BN 128
#define BK 64             // fp16 elems per k-chunk (128 bytes/row, SW128)
#define KT (DIM_K / BK)   // 64 k-iterations
#define MT (DIM_M / BM)   // 64 m-tiles
#define NT (DIM_N / BN)   // 32 n-tiles

#define A_TILE_BYTES  (BM * 128)          // 16384
#define W_TILE_BYTES  (BN * 128)          // 16384
#define STAGE_BYTES   (A_TILE_BYTES + W_TILE_BYTES)      // 32768
#define NSTAGES 3
#define SMEM_DYN (1024 + NSTAGES * STAGE_BYTES)          // 99328 (x2 CTAs = 198.7KB/SM)

#define OFF_FULL(s)  ((s) * 8)
#define STAGE_BASE(s) (1024 + (s) * STAGE_BYTES)
#define ST_A 0
#define ST_W A_TILE_BYTES

// ---------------- scratch (device globals; allocation-free rule) ------------
__device__ __align__(1024) unsigned char g_A [(unsigned long long)MT * KT * A_TILE_BYTES];   // 64 MB
__device__ __align__(1024) unsigned char g_Wt[(unsigned long long)NT * KT * W_TILE_BYTES];   // 32 MB
__device__ float g_rowsum[DIM_M];

// ---------------- PTX helpers (generic-target safe) ----------------
__device__ __forceinline__ uint32_t smem_u32(const void* p) {
    uint32_t a;
    asm("{ .reg .u64 t; cvta.to.shared.u64 t, %1; cvt.u32.u64 %0, t; }" : "=r"(a) : "l"(p));
    return a;
}
__device__ __forceinline__ uint32_t swz128(uint32_t o) { return o ^ ((o >> 3) & 0x70); }

#define MBAR_INIT(addr, cnt) \
    asm volatile("mbarrier.init.shared.b64 [%0], %1;" :: "r"(addr), "r"(cnt) : "memory")
#define MBAR_EXPECT_TX(addr, bytes) \
    asm volatile("mbarrier.arrive.expect_tx.shared.b64 _, [%0], %1;" :: "r"(addr), "r"(bytes) : "memory")
#define MBAR_WAIT(addr, parity) do {                                                  \
    uint32_t _m = (addr); uint32_t _p = (parity); uint32_t _d;                        \
    asm volatile("{\n\t.reg .pred p;\n\t"                                             \
        "mbarrier.try_wait.parity.acquire.cta.shared::cta.b64 p, [%1], %2;\n\t"       \
        "selp.b32 %0, 1, 0, p;\n\t}"                                                  \
        : "=r"(_d) : "r"(_m), "r"(_p) : "memory");                                    \
    if (!_d) {                                                                        \
        asm volatile("{\n\t.reg .pred P1;\n\t"                                        \
            "WL_%=:\n\t"                                                              \
            "mbarrier.try_wait.parity.acquire.cta.shared::cta.b64 P1, [%0], %1, 0x989680;\n\t" \
            "@P1 bra.uni WD_%=;\n\t"                                                  \
            "bra.uni WL_%=;\n\t"                                                      \
            "WD_%=:\n\t}" :: "r"(_m), "r"(_p) : "memory");                            \
    }                                                                                 \
} while (0)

__device__ __forceinline__ void bulk_g2s(uint32_t dst, const void* src, uint32_t bytes, uint32_t mbar) {
    asm volatile(
        "cp.async.bulk.shared::cluster.global.mbarrier::complete_tx::bytes [%0], [%1], %2, [%3];"
        :: "r"(dst), "l"(src), "r"(bytes), "r"(mbar) : "memory");
}

__device__ __forceinline__ void ldsm4(uint32_t* r, uint32_t addr) {
    asm volatile("ldmatrix.sync.aligned.m8n8.x4.shared.b16 {%0,%1,%2,%3}, [%4];"
        : "=r"(r[0]), "=r"(r[1]), "=r"(r[2]), "=r"(r[3]) : "r"(addr));
}

__device__ __forceinline__ void mma_fp16(float* c, const uint32_t* a, uint32_t b0, uint32_t b1) {
    asm volatile(
        "mma.sync.aligned.m16n8k16.row.col.f32.f16.f16.f32 "
        "{%0,%1,%2,%3}, {%4,%5,%6,%7}, {%8,%9}, {%0,%1,%2,%3};"
        : "+f"(c[0]), "+f"(c[1]), "+f"(c[2]), "+f"(c[3])
        : "r"(a[0]), "r"(a[1]), "r"(a[2]), "r"(a[3]), "r"(b0), "r"(b1));
}

// ------------- fused prolog: W int32->fp16 tiles | A fp32->fp16 tiles+rowsums
// Blocks [0, DIM_N)          : one W row each  (exact int8-in-fp16)
// Blocks [DIM_N, DIM_N+DIM_M): one A row each  (fp16 round + fp32 rowsum)
__global__ void __launch_bounds__(512) k_convert(const int* __restrict__ w,
                                                 const float* __restrict__ x) {
    int bid = blockIdx.x;
    int t = threadIdx.x;       // 0..511, handles 8 consecutive k
    if (bid < DIM_N) {
        int n = bid;
        const int4* row = reinterpret_cast<const int4*>(w + (size_t)n * DIM_K);
        int4 a = row[2 * t], b = row[2 * t + 1];
        int v[8] = {a.x, a.y, a.z, a.w, b.x, b.y, b.z, b.w};
        union { __half h[8]; uint4 u; } q;
#pragma unroll
        for (int i = 0; i < 8; i++) q.h[i] = __float2half_rn((float)v[i]);   // exact for int8 range
        int k0 = t * 8;
        int kt = k0 >> 6, c = k0 & 63;
        int ntile = n >> 7, r = n & 127;
        size_t tile = ((size_t)(ntile * KT + kt)) << 14;        // * 16384
        uint32_t off = swz128((uint32_t)(r * 128 + c * 2));
        *reinterpret_cast<uint4*>(g_Wt + tile + off) = q.u;
    } else {
        int m = bid - DIM_N;
        const float4* row = reinterpret_cast<const float4*>(x + (size_t)m * DIM_K);
        float4 f0 = row[2 * t], f1 = row[2 * t + 1];
        float v[8] = {f0.x, f0.y, f0.z, f0.w, f1.x, f1.y, f1.z, f1.w};
        union { __half h[8]; uint4 u; } q;
        float s = 0.f;
#pragma unroll
        for (int i = 0; i < 8; i++) {
            s += v[i];
            q.h[i] = __float2half_rn(v[i]);
        }
        int k0 = t * 8;
        int kt = k0 >> 6, c = k0 & 63;
        int mt = m >> 7, r = m & 127;
        size_t tile = ((size_t)(mt * KT + kt)) << 14;            // * 16384
        uint32_t off = swz128((uint32_t)(r * 128 + c * 2));
        *reinterpret_cast<uint4*>(g_A + tile + off) = q.u;

        // block-reduce row sum (for zero_point correction)
#pragma unroll
        for (int o = 16; o > 0; o >>= 1) s += __shfl_down_sync(0xFFFFFFFFu, s, o);
        __shared__ float sred[16];
        if ((t & 31) == 0) sred[t >> 5] = s;
        __syncthreads();
        if (t == 0) {
            float tot = 0.f;
#pragma unroll
            for (int i = 0; i < 16; i++) tot += sred[i];
            g_rowsum[m] = tot;
        }
    }
}

// -------- main GEMM: fp16 mma.sync, CTA 128x128, 8 warps (32x64), 2 CTAs/SM --
__global__ void __launch_bounds__(256, 2)
k_gemm(const float* __restrict__ scale, const float* __restrict__ zp,
       const float* __restrict__ bias, float* __restrict__ out) {
    extern __shared__ unsigned char smem[];
    const uint32_t sb = smem_u32(smem);
    const int tid  = threadIdx.x;
    const int wid  = tid >> 5;
    const int lane = tid & 31;
    const int ntile = blockIdx.x;     // 0..31
    const int mtile = blockIdx.y;     // 0..63

    const int warpM = wid >> 1;       // 0..3 -> m offset warpM*32
    const int warpN = wid & 1;        // 0..1 -> n offset warpN*64

    if (tid == 0) {
#pragma unroll
        for (int s = 0; s < NSTAGES; ++s) MBAR_INIT(sb + OFF_FULL(s), 1);
    }
    __syncthreads();

    const unsigned char* gA = g_A  + ((size_t)mtile * KT) * A_TILE_BYTES;
    const unsigned char* gW = g_Wt + ((size_t)ntile * KT) * W_TILE_BYTES;

    // prefill all stages
    if (tid == 0) {
#pragma unroll
        for (int it = 0; it < NSTAGES; ++it) {
            uint32_t full = sb + OFF_FULL(it);
            MBAR_EXPECT_TX(full, STAGE_BYTES);
            uint32_t base = sb + STAGE_BASE(it);
            bulk_g2s(base + ST_A, gA + (size_t)it * A_TILE_BYTES, A_TILE_BYTES, full);
            bulk_g2s(base + ST_W, gW + (size_t)it * W_TILE_BYTES, W_TILE_BYTES, full);
        }
    }

    float acc[2][8][4];               // [mf 16-row][n8 block][frag]
#pragma unroll
    for (int i = 0; i < 2; ++i)
#pragma unroll
        for (int j = 0; j < 8; ++j)
#pragma unroll
            for (int q = 0; q < 4; ++q) acc[i][j][q] = 0.f;

    // Hoisted swizzle math: swz128(r*128 + c2) = r*128 + (c2 ^ ((r&7)<<4)).
    const int lr = lane & 15;              // ldmatrix row
    const int lc = (lane >> 4) << 3;       // 0 or 8 (k offset within 16)
    uint32_t aRow[2], aKey[2], wRow[4], wKey[4];
#pragma unroll
    for (int mf = 0; mf < 2; ++mf) {
        int r = warpM * 32 + mf * 16 + lr;
        aRow[mf] = (uint32_t)(r * 128);
        aKey[mf] = (uint32_t)((r & 7) << 4);
    }
#pragma unroll
    for (int nf = 0; nf < 4; ++nf) {
        int r = warpN * 64 + nf * 16 + lr;
        wRow[nf] = (uint32_t)(r * 128);
        wKey[nf] = (uint32_t)((r & 7) << 4);
    }

    uint32_t af[2][4], bw[4][4];   // single-buffered fragments (R6: DB = no gain)

    int s = 0, ph = 0;
    for (int it = 0; it < KT; ++it) {
        MBAR_WAIT(sb + OFF_FULL(s), ph);
        const uint32_t base = sb + STAGE_BASE(s);
        const uint32_t aB = base + ST_A;
        const uint32_t wB = base + ST_W;

#pragma unroll
        for (int ks = 0; ks < 4; ++ks) {
            const uint32_t c2 = (uint32_t)((ks * 16 + lc) * 2);
#pragma unroll
            for (int mf = 0; mf < 2; ++mf)
                ldsm4(af[mf], aB + aRow[mf] + (c2 ^ aKey[mf]));
#pragma unroll
            for (int nf = 0; nf < 4; ++nf)
                ldsm4(bw[nf], wB + wRow[nf] + (c2 ^ wKey[nf]));
#pragma unroll
            for (int mf = 0; mf < 2; ++mf) {
#pragma unroll
                for (int nf = 0; nf < 4; ++nf) {
                    mma_fp16(acc[mf][2 * nf + 0], af[mf], bw[nf][0], bw[nf][2]);
                    mma_fp16(acc[mf][2 * nf + 1], af[mf], bw[nf][1], bw[nf][3]);
                }
            }
        }

        __syncthreads();                   // all warps done reading stage s
        if (tid == 0 && it + NSTAGES < KT) {
            int nit = it + NSTAGES;
            uint32_t full = sb + OFF_FULL(s);
            MBAR_EXPECT_TX(full, STAGE_BYTES);
            uint32_t nb = sb + STAGE_BASE(s);
            bulk_g2s(nb + ST_A, gA + (size_t)nit * A_TILE_BYTES, A_TILE_BYTES, full);
            bulk_g2s(nb + ST_W, gW + (size_t)nit * W_TILE_BYTES, W_TILE_BYTES, full);
        }
        if (++s == NSTAGES) { s = 0; ph ^= 1; }
    }

    // -------- epilogue: registers -> gmem (sector-complete float2 stores) ----
    const int tq = lane >> 2;   // 0..7 row within 8
    const int tr = lane & 3;    // col pair
    const int m_base = mtile * BM + warpM * 32;
    const int n_base = ntile * BN + warpN * 64;

#pragma unroll
    for (int mf = 0; mf < 2; ++mf) {
        int r0 = m_base + mf * 16 + tq;
        int r1 = r0 + 8;
        float rs0 = g_rowsum[r0];
        float rs1 = g_rowsum[r1];
        float* o0 = out + (size_t)r0 * DIM_N;
        float* o1 = out + (size_t)r1 * DIM_N;
#pragma unroll
        for (int j = 0; j < 8; ++j) {
            int n = n_base + j * 8 + 2 * tr;
            float2 sc = *reinterpret_cast<const float2*>(scale + n);
            float2 zq = *reinterpret_cast<const float2*>(zp + n);
            float2 bb = *reinterpret_cast<const float2*>(bias + n);
            float* c = acc[mf][j];
            float2 v0, v1;
            v0.x = c[0] * sc.x + bb.x - sc.x * zq.x * rs0;
            v0.y = c[1] * sc.y + bb.y - sc.y * zq.y * rs0;
            v1.x = c[2] * sc.x + bb.x - sc.x * zq.x * rs1;
            v1.y = c[3] * sc.y + bb.y - sc.y * zq.y * rs1;
            *reinterpret_cast<float2*>(o0 + n) = v0;
            *reinterpret_cast<float2*>(o1 + n) = v1;
        }
    }
}

// ---------------- launch ----------------
extern "C" void kernel_launch(void* const* d_in, const int* in_sizes, int n_in,
                              void* d_out, int out_size) {
    const float* input  = (const float*)d_in[0];   // [4,2048,4096] fp32
    const int*   w_int  = (const int*)  d_in[1];   // [4096,4096] int32
    const float* scale  = (const float*)d_in[2];   // [4096,1]
    const float* zp     = (const float*)d_in[3];   // [4096,1]
    const float* bias   = (const float*)d_in[4];   // [4096]
    float* out = (float*)d_out;

    k_convert<<<DIM_N + DIM_M, 512>>>(w_int, input);

    cudaFuncSetAttribute(k_gemm, cudaFuncAttributeMaxDynamicSharedMemorySize, SMEM_DYN);

    dim3 grid(NT, MT);   // x = n-tile fastest: co-resident CTAs share A tiles in L2
    k_gemm<<<grid, 256, SMEM_DYN>>>(scale, zp, bias, out);
}

// round 12
// speedup vs baseline: 1.0893x; 1.0197x over previous
// FastQuantizedLinear on GB300 (sm_103a host, compute_103 generic PTX target)
// out[8192,4096] = x[8192,4096] @ ((W_int8 - zp) * s)^T + bias
// Single-pass fp16 HMMA (W exact in fp16, x rounded: rel_err ~2e-4 < 1e-3).
// R12: replace per-iter __syncthreads with asymmetric named barrier:
// warps 1-7 bar.arrive (non-blocking) after their last MMA of the stage;
// warp 0 bar.sync, then tid0 reissues the bulk copy. 3 rotating barrier ids
// (= stage index) keep generations distinct under warp skew (max 2 iters,
// gated by the mbarrier full-wait on stages the producer hasn't filled).
#include <cuda_runtime.h>
#include <cuda_fp16.h>
#include <cstdint>

// ---------------- problem constants ----------------
#define DIM_M 8192   // B*S
#define DIM_N 4096   // OUT
#define DIM_K 4096   // IN

#define BM 128
#define BN 128
#define BK 64             // fp16 elems per k-chunk (128 bytes/row, SW128)
#define KT (DIM_K / BK)   // 64 k-iterations
#define MT (DIM_M / BM)   // 64 m-tiles
#define NT (DIM_N / BN)   // 32 n-tiles

#define A_TILE_BYTES  (BM * 128)          // 16384
#define W_TILE_BYTES  (BN * 128)          // 16384
#define STAGE_BYTES   (A_TILE_BYTES + W_TILE_BYTES)      // 32768
#define NSTAGES 3
#define SMEM_DYN (1024 + NSTAGES * STAGE_BYTES)          // 99328 (x2 CTAs = 198.7KB/SM)

#define OFF_FULL(s)  ((s) * 8)
#define STAGE_BASE(s) (1024 + (s) * STAGE_BYTES)
#define ST_A 0
#define ST_W A_TILE_BYTES

// ---------------- scratch (device globals; allocation-free rule) ------------
__device__ __align__(1024) unsigned char g_A [(unsigned long long)MT * KT * A_TILE_BYTES];   // 64 MB
__device__ __align__(1024) unsigned char g_Wt[(unsigned long long)NT * KT * W_TILE_BYTES];   // 32 MB
__device__ float g_rowsum[DIM_M];

// ---------------- PTX helpers (generic-target safe) ----------------
__device__ __forceinline__ uint32_t smem_u32(const void* p) {
    uint32_t a;
    asm("{ .reg .u64 t; cvta.to.shared.u64 t, %1; cvt.u32.u64 %0, t; }" : "=r"(a) : "l"(p));
    return a;
}
__device__ __forceinline__ uint32_t swz128(uint32_t o) { return o ^ ((o >> 3) & 0x70); }

#define MBAR_INIT(addr, cnt) \
    asm volatile("mbarrier.init.shared.b64 [%0], %1;" :: "r"(addr), "r"(cnt) : "memory")
#define MBAR_EXPECT_TX(addr, bytes) \
    asm volatile("mbarrier.arrive.expect_tx.shared.b64 _, [%0], %1;" :: "r"(addr), "r"(bytes) : "memory")
#define MBAR_WAIT(addr, parity) do {                                                  \
    uint32_t _m = (addr); uint32_t _p = (parity); uint32_t _d;                        \
    asm volatile("{\n\t.reg .pred p;\n\t"                                             \
        "mbarrier.try_wait.parity.acquire.cta.shared::cta.b64 p, [%1], %2;\n\t"       \
        "selp.b32 %0, 1, 0, p;\n\t}"                                                  \
        : "=r"(_d) : "r"(_m), "r"(_p) : "memory");                                    \
    if (!_d) {                                                                        \
        asm volatile("{\n\t.reg .pred P1;\n\t"                                        \
            "WL_%=:\n\t"                                                              \
            "mbarrier.try_wait.parity.acquire.cta.shared::cta.b64 P1, [%0], %1, 0x989680;\n\t" \
            "@P1 bra.uni WD_%=;\n\t"                                                  \
            "bra.uni WL_%=;\n\t"                                                      \
            "WD_%=:\n\t}" :: "r"(_m), "r"(_p) : "memory");                            \
    }                                                                                 \
} while (0)

#define BAR_ARRIVE(id) \
    asm volatile("bar.arrive %0, 256;" :: "r"(id) : "memory")
#define BAR_SYNC(id) \
    asm volatile("bar.sync %0, 256;" :: "r"(id) : "memory")

__device__ __forceinline__ void bulk_g2s(uint32_t dst, const void* src, uint32_t bytes, uint32_t mbar) {
    asm volatile(
        "cp.async.bulk.shared::cluster.global.mbarrier::complete_tx::bytes [%0], [%1], %2, [%3];"
        :: "r"(dst), "l"(src), "r"(bytes), "r"(mbar) : "memory");
}

__device__ __forceinline__ void ldsm4(uint32_t* r, uint32_t addr) {
    asm volatile("ldmatrix.sync.aligned.m8n8.x4.shared.b16 {%0,%1,%2,%3}, [%4];"
        : "=r"(r[0]), "=r"(r[1]), "=r"(r[2]), "=r"(r[3]) : "r"(addr));
}

__device__ __forceinline__ void mma_fp16(float* c, const uint32_t* a, uint32_t b0, uint32_t b1) {
    asm volatile(
        "mma.sync.aligned.m16n8k16.row.col.f32.f16.f16.f32 "
        "{%0,%1,%2,%3}, {%4,%5,%6,%7}, {%8,%9}, {%0,%1,%2,%3};"
        : "+f"(c[0]), "+f"(c[1]), "+f"(c[2]), "+f"(c[3])
        : "r"(a[0]), "r"(a[1]), "r"(a[2]), "r"(a[3]), "r"(b0), "r"(b1));
}

// ------------- fused prolog: W int32->fp16 tiles | A fp32->fp16 tiles+rowsums
// Blocks [0, DIM_N)          : one W row each  (exact int8-in-fp16)
// Blocks [DIM_N, DIM_N+DIM_M): one A row each  (fp16 round + fp32 rowsum)
__global__ void __launch_bounds__(512) k_convert(const int* __restrict__ w,
                                                 const float* __restrict__ x) {
    int bid = blockIdx.x;
    int t = threadIdx.x;       // 0..511, handles 8 consecutive k
    if (bid < DIM_N) {
        int n = bid;
        const int4* row = reinterpret_cast<const int4*>(w + (size_t)n * DIM_K);
        int4 a = row[2 * t], b = row[2 * t + 1];
        int v[8] = {a.x, a.y, a.z, a.w, b.x, b.y, b.z, b.w};
        union { __half h[8]; uint4 u; } q;
#pragma unroll
        for (int i = 0; i < 8; i++) q.h[i] = __float2half_rn((float)v[i]);   // exact for int8 range
        int k0 = t * 8;
        int kt = k0 >> 6, c = k0 & 63;
        int ntile = n >> 7, r = n & 127;
        size_t tile = ((size_t)(ntile * KT + kt)) << 14;        // * 16384
        uint32_t off = swz128((uint32_t)(r * 128 + c * 2));
        *reinterpret_cast<uint4*>(g_Wt + tile + off) = q.u;
    } else {
        int m = bid - DIM_N;
        const float4* row = reinterpret_cast<const float4*>(x + (size_t)m * DIM_K);
        float4 f0 = row[2 * t], f1 = row[2 * t + 1];
        float v[8] = {f0.x, f0.y, f0.z, f0.w, f1.x, f1.y, f1.z, f1.w};
        union { __half h[8]; uint4 u; } q;
        float s = 0.f;
#pragma unroll
        for (int i = 0; i < 8; i++) {
            s += v[i];
            q.h[i] = __float2half_rn(v[i]);
        }
        int k0 = t * 8;
        int kt = k0 >> 6, c = k0 & 63;
        int mt = m >> 7, r = m & 127;
        size_t tile = ((size_t)(mt * KT + kt)) << 14;            // * 16384
        uint32_t off = swz128((uint32_t)(r * 128 + c * 2));
        *reinterpret_cast<uint4*>(g_A + tile + off) = q.u;

        // block-reduce row sum (for zero_point correction)
#pragma unroll
        for (int o = 16; o > 0; o >>= 1) s += __shfl_down_sync(0xFFFFFFFFu, s, o);
        __shared__ float sred[16];
        if ((t & 31) == 0) sred[t >> 5] = s;
        __syncthreads();
        if (t == 0) {
            float tot = 0.f;
#pragma unroll
            for (int i = 0; i < 16; i++) tot += sred[i];
            g_rowsum[m] = tot;
        }
    }
}

// -------- main GEMM: fp16 mma.sync, CTA 128x128, 8 warps (32x64), 2 CTAs/SM --
// Stage release: consumers bar.arrive, producer warp bar.sync + reissue.
__global__ void __launch_bounds__(256, 2)
k_gemm(const float* __restrict__ scale, const float* __restrict__ zp,
       const float* __restrict__ bias, float* __restrict__ out) {
    extern __shared__ unsigned char smem[];
    const uint32_t sb = smem_u32(smem);
    const int tid  = threadIdx.x;
    const int wid  = tid >> 5;
    const int lane = tid & 31;
    const int ntile = blockIdx.x;     // 0..31
    const int mtile = blockIdx.y;     // 0..63

    const int warpM = wid >> 1;       // 0..3 -> m offset warpM*32
    const int warpN = wid & 1;        // 0..1 -> n offset warpN*64

    if (tid == 0) {
#pragma unroll
        for (int s = 0; s < NSTAGES; ++s) MBAR_INIT(sb + OFF_FULL(s), 1);
    }
    __syncthreads();

    const unsigned char* gA = g_A  + ((size_t)mtile * KT) * A_TILE_BYTES;
    const unsigned char* gW = g_Wt + ((size_t)ntile * KT) * W_TILE_BYTES;

    // prefill all stages
    if (tid == 0) {
#pragma unroll
        for (int it = 0; it < NSTAGES; ++it) {
            uint32_t full = sb + OFF_FULL(it);
            MBAR_EXPECT_TX(full, STAGE_BYTES);
            uint32_t base = sb + STAGE_BASE(it);
            bulk_g2s(base + ST_A, gA + (size_t)it * A_TILE_BYTES, A_TILE_BYTES, full);
            bulk_g2s(base + ST_W, gW + (size_t)it * W_TILE_BYTES, W_TILE_BYTES, full);
        }
    }

    float acc[2][8][4];               // [mf 16-row][n8 block][frag]
#pragma unroll
    for (int i = 0; i < 2; ++i)
#pragma unroll
        for (int j = 0; j < 8; ++j)
#pragma unroll
            for (int q = 0; q < 4; ++q) acc[i][j][q] = 0.f;

    // Hoisted swizzle math: swz128(r*128 + c2) = r*128 + (c2 ^ ((r&7)<<4)).
    const int lr = lane & 15;              // ldmatrix row
    const int lc = (lane >> 4) << 3;       // 0 or 8 (k offset within 16)
    uint32_t aRow[2], aKey[2], wRow[4], wKey[4];
#pragma unroll
    for (int mf = 0; mf < 2; ++mf) {
        int r = warpM * 32 + mf * 16 + lr;
        aRow[mf] = (uint32_t)(r * 128);
        aKey[mf] = (uint32_t)((r & 7) << 4);
    }
#pragma unroll
    for (int nf = 0; nf < 4; ++nf) {
        int r = warpN * 64 + nf * 16 + lr;
        wRow[nf] = (uint32_t)(r * 128);
        wKey[nf] = (uint32_t)((r & 7) << 4);
    }

    uint32_t af[2][4], bw[4][4];   // single-buffered fragments

    int s = 0, ph = 0;
    for (int it = 0; it < KT; ++it) {
        MBAR_WAIT(sb + OFF_FULL(s), ph);
        const uint32_t base = sb + STAGE_BASE(s);
        const uint32_t aB = base + ST_A;
        const uint32_t wB = base + ST_W;

#pragma unroll
        for (int ks = 0; ks < 4; ++ks) {
            const uint32_t c2 = (uint32_t)((ks * 16 + lc) * 2);
#pragma unroll
            for (int mf = 0; mf < 2; ++mf)
                ldsm4(af[mf], aB + aRow[mf] + (c2 ^ aKey[mf]));
#pragma unroll
            for (int nf = 0; nf < 4; ++nf)
                ldsm4(bw[nf], wB + wRow[nf] + (c2 ^ wKey[nf]));
#pragma unroll
            for (int mf = 0; mf < 2; ++mf) {
#pragma unroll
                for (int nf = 0; nf < 4; ++nf) {
                    mma_fp16(acc[mf][2 * nf + 0], af[mf], bw[nf][0], bw[nf][2]);
                    mma_fp16(acc[mf][2 * nf + 1], af[mf], bw[nf][1], bw[nf][3]);
                }
            }
        }

        // Stage release. All MMAs consuming stage s issued above -> this
        // warp's LDSM reads of stage s are complete. Consumers don't block;
        // only warp 0 waits for all 8 warps, then tid0 overwrites stage s.
        // Barrier id = stage index (1..3): generations stay distinct because
        // a warp can only reach iter it+NSTAGES (same id) after this
        // generation completed (its stage refill is gated by the bar.sync).
        if (wid == 0) {
            BAR_SYNC(1 + s);
            if (tid == 0 && it + NSTAGES < KT) {
                int nit = it + NSTAGES;
                uint32_t full = sb + OFF_FULL(s);
                MBAR_EXPECT_TX(full, STAGE_BYTES);
                uint32_t nb = sb + STAGE_BASE(s);
                bulk_g2s(nb + ST_A, gA + (size_t)nit * A_TILE_BYTES, A_TILE_BYTES, full);
                bulk_g2s(nb + ST_W, gW + (size_t)nit * W_TILE_BYTES, W_TILE_BYTES, full);
            }
        } else {
            BAR_ARRIVE(1 + s);
        }
        if (++s == NSTAGES) { s = 0; ph ^= 1; }
    }

    // -------- epilogue: registers -> gmem (sector-complete float2 stores) ----
    const int tq = lane >> 2;   // 0..7 row within 8
    const int tr = lane & 3;    // col pair
    const int m_base = mtile * BM + warpM * 32;
    const int n_base = ntile * BN + warpN * 64;

#pragma unroll
    for (int mf = 0; mf < 2; ++mf) {
        int r0 = m_base + mf * 16 + tq;
        int r1 = r0 + 8;
        float rs0 = g_rowsum[r0];
        float rs1 = g_rowsum[r1];
        float* o0 = out + (size_t)r0 * DIM_N;
        float* o1 = out + (size_t)r1 * DIM_N;
#pragma unroll
        for (int j = 0; j < 8; ++j) {
            int n = n_base + j * 8 + 2 * tr;
            float2 sc = *reinterpret_cast<const float2*>(scale + n);
            float2 zq = *reinterpret_cast<const float2*>(zp + n);
            float2 bb = *reinterpret_cast<const float2*>(bias + n);
            float* c = acc[mf][j];
            float2 v0, v1;
            v0.x = c[0] * sc.x + bb.x - sc.x * zq.x * rs0;
            v0.y = c[1] * sc.y + bb.y - sc.y * zq.y * rs0;
            v1.x = c[2] * sc.x + bb.x - sc.x * zq.x * rs1;
            v1.y = c[3] * sc.y + bb.y - sc.y * zq.y * rs1;
            *reinterpret_cast<float2*>(o0 + n) = v0;
            *reinterpret_cast<float2*>(o1 + n) = v1;
        }
    }
}

// ---------------- launch ----------------
extern "C" void kernel_launch(void* const* d_in, const int* in_sizes, int n_in,
                              void* d_out, int out_size) {
    const float* input  = (const float*)d_in[0];   // [4,2048,4096] fp32
    const int*   w_int  = (const int*)  d_in[1];   // [4096,4096] int32
    const float* scale  = (const float*)d_in[2];   // [4096,1]
    const float* zp     = (const float*)d_in[3];   // [4096,1]
    const float* bias   = (const float*)d_in[4];   // [4096]
    float* out = (float*)d_out;

    k_convert<<<DIM_N + DIM_M, 512>>>(w_int, input);

    cudaFuncSetAttribute(k_gemm, cudaFuncAttributeMaxDynamicSharedMemorySize, SMEM_DYN);

    dim3 grid(NT, MT);   // x = n-tile fastest: co-resident CTAs share A tiles in L2
    k_gemm<<<grid, 256, SMEM_DYN>>>(scale, zp, bias, out);
}

// round 13
// speedup vs baseline: 1.1309x; 1.0382x over previous
// FastQuantizedLinear on GB300 (sm_103a host, compute_103 generic PTX target)
// out[8192,4096] = x[8192,4096] @ ((W_int8 - zp) * s)^T + bias
// Single-pass fp16 HMMA (W exact in fp16, x rounded: rel_err ~2e-4 < 1e-3).
// R13: issue-port decongestion. ncu: tensor 73.4%, alu 30% -> ~400 ALU instrs
// per SMSP-slot contend with HMMA issue. (1) all 24 LDSM offsets precomputed
// (swizzle XOR hoisted out of the mainloop entirely); (2) KT loop unrolled by
// NSTAGES=3 so stage index/base/barrier-id/parity are compile-time per body.
#include <cuda_runtime.h>
#include <cuda_fp16.h>
#include <cstdint>

// ---------------- problem constants ----------------
#define DIM_M 8192   // B*S
#define DIM_N 4096   // OUT
#define DIM_K 4096   // IN

#define BM 128
#define BN 128
#define BK 64             // fp16 elems per k-chunk (128 bytes/row, SW128)
#define KT (DIM_K / BK)   // 64 k-iterations
#define MT (DIM_M / BM)   // 64 m-tiles
#define NT (DIM_N / BN)   // 32 n-tiles

#define A_TILE_BYTES  (BM * 128)          // 16384
#define W_TILE_BYTES  (BN * 128)          // 16384
#define STAGE_BYTES   (A_TILE_BYTES + W_TILE_BYTES)      // 32768
#define NSTAGES 3
#define SMEM_DYN (1024 + NSTAGES * STAGE_BYTES)          // 99328 (x2 CTAs = 198.7KB/SM)

#define OFF_FULL(s)  ((s) * 8)
#define STAGE_BASE(s) (1024 + (s) * STAGE_BYTES)
#define ST_A 0
#define ST_W A_TILE_BYTES

// ---------------- scratch (device globals; allocation-free rule) ------------
__device__ __align__(1024) unsigned char g_A [(unsigned long long)MT * KT * A_TILE_BYTES];   // 64 MB
__device__ __align__(1024) unsigned char g_Wt[(unsigned long long)NT * KT * W_TILE_BYTES];   // 32 MB
__device__ float g_rowsum[DIM_M];

// ---------------- PTX helpers (generic-target safe) ----------------
__device__ __forceinline__ uint32_t smem_u32(const void* p) {
    uint32_t a;
    asm("{ .reg .u64 t; cvta.to.shared.u64 t, %1; cvt.u32.u64 %0, t; }" : "=r"(a) : "l"(p));
    return a;
}
__device__ __forceinline__ uint32_t swz128(uint32_t o) { return o ^ ((o >> 3) & 0x70); }

#define MBAR_INIT(addr, cnt) \
    asm volatile("mbarrier.init.shared.b64 [%0], %1;" :: "r"(addr), "r"(cnt) : "memory")
#define MBAR_EXPECT_TX(addr, bytes) \
    asm volatile("mbarrier.arrive.expect_tx.shared.b64 _, [%0], %1;" :: "r"(addr), "r"(bytes) : "memory")
#define MBAR_WAIT(addr, parity) do {                                                  \
    uint32_t _m = (addr); uint32_t _p = (parity); uint32_t _d;                        \
    asm volatile("{\n\t.reg .pred p;\n\t"                                             \
        "mbarrier.try_wait.parity.acquire.cta.shared::cta.b64 p, [%1], %2;\n\t"       \
        "selp.b32 %0, 1, 0, p;\n\t}"                                                  \
        : "=r"(_d) : "r"(_m), "r"(_p) : "memory");                                    \
    if (!_d) {                                                                        \
        asm volatile("{\n\t.reg .pred P1;\n\t"                                        \
            "WL_%=:\n\t"                                                              \
            "mbarrier.try_wait.parity.acquire.cta.shared::cta.b64 P1, [%0], %1, 0x989680;\n\t" \
            "@P1 bra.uni WD_%=;\n\t"                                                  \
            "bra.uni WL_%=;\n\t"                                                      \
            "WD_%=:\n\t}" :: "r"(_m), "r"(_p) : "memory");                            \
    }                                                                                 \
} while (0)

#define BAR_ARRIVE(id) \
    asm volatile("bar.arrive %0, 256;" :: "n"(id) : "memory")
#define BAR_SYNC(id) \
    asm volatile("bar.sync %0, 256;" :: "n"(id) : "memory")

__device__ __forceinline__ void bulk_g2s(uint32_t dst, const void* src, uint32_t bytes, uint32_t mbar) {
    asm volatile(
        "cp.async.bulk.shared::cluster.global.mbarrier::complete_tx::bytes [%0], [%1], %2, [%3];"
        :: "r"(dst), "l"(src), "r"(bytes), "r"(mbar) : "memory");
}

__device__ __forceinline__ void ldsm4(uint32_t* r, uint32_t addr) {
    asm volatile("ldmatrix.sync.aligned.m8n8.x4.shared.b16 {%0,%1,%2,%3}, [%4];"
        : "=r"(r[0]), "=r"(r[1]), "=r"(r[2]), "=r"(r[3]) : "r"(addr));
}

__device__ __forceinline__ void mma_fp16(float* c, const uint32_t* a, uint32_t b0, uint32_t b1) {
    asm volatile(
        "mma.sync.aligned.m16n8k16.row.col.f32.f16.f16.f32 "
        "{%0,%1,%2,%3}, {%4,%5,%6,%7}, {%8,%9}, {%0,%1,%2,%3};"
        : "+f"(c[0]), "+f"(c[1]), "+f"(c[2]), "+f"(c[3])
        : "r"(a[0]), "r"(a[1]), "r"(a[2]), "r"(a[3]), "r"(b0), "r"(b1));
}

// ------------- fused prolog: W int32->fp16 tiles | A fp32->fp16 tiles+rowsums
__global__ void __launch_bounds__(512) k_convert(const int* __restrict__ w,
                                                 const float* __restrict__ x) {
    int bid = blockIdx.x;
    int t = threadIdx.x;       // 0..511, handles 8 consecutive k
    if (bid < DIM_N) {
        int n = bid;
        const int4* row = reinterpret_cast<const int4*>(w + (size_t)n * DIM_K);
        int4 a = row[2 * t], b = row[2 * t + 1];
        int v[8] = {a.x, a.y, a.z, a.w, b.x, b.y, b.z, b.w};
        union { __half h[8]; uint4 u; } q;
#pragma unroll
        for (int i = 0; i < 8; i++) q.h[i] = __float2half_rn((float)v[i]);   // exact for int8 range
        int k0 = t * 8;
        int kt = k0 >> 6, c = k0 & 63;
        int ntile = n >> 7, r = n & 127;
        size_t tile = ((size_t)(ntile * KT + kt)) << 14;        // * 16384
        uint32_t off = swz128((uint32_t)(r * 128 + c * 2));
        *reinterpret_cast<uint4*>(g_Wt + tile + off) = q.u;
    } else {
        int m = bid - DIM_N;
        const float4* row = reinterpret_cast<const float4*>(x + (size_t)m * DIM_K);
        float4 f0 = row[2 * t], f1 = row[2 * t + 1];
        float v[8] = {f0.x, f0.y, f0.z, f0.w, f1.x, f1.y, f1.z, f1.w};
        union { __half h[8]; uint4 u; } q;
        float s = 0.f;
#pragma unroll
        for (int i = 0; i < 8; i++) {
            s += v[i];
            q.h[i] = __float2half_rn(v[i]);
        }
        int k0 = t * 8;
        int kt = k0 >> 6, c = k0 & 63;
        int mt = m >> 7, r = m & 127;
        size_t tile = ((size_t)(mt * KT + kt)) << 14;            // * 16384
        uint32_t off = swz128((uint32_t)(r * 128 + c * 2));
        *reinterpret_cast<uint4*>(g_A + tile + off) = q.u;

        // block-reduce row sum (for zero_point correction)
#pragma unroll
        for (int o = 16; o > 0; o >>= 1) s += __shfl_down_sync(0xFFFFFFFFu, s, o);
        __shared__ float sred[16];
        if ((t & 31) == 0) sred[t >> 5] = s;
        __syncthreads();
        if (t == 0) {
            float tot = 0.f;
#pragma unroll
            for (int i = 0; i < 16; i++) tot += sred[i];
            g_rowsum[m] = tot;
        }
    }
}

// -------- main GEMM: fp16 mma.sync, CTA 128x128, 8 warps (32x64), 2 CTAs/SM --
// KT loop unrolled x3 (stage index compile-time); LDSM offsets precomputed.
__global__ void __launch_bounds__(256, 2)
k_gemm(const float* __restrict__ scale, const float* __restrict__ zp,
       const float* __restrict__ bias, float* __restrict__ out) {
    extern __shared__ unsigned char smem[];
    const uint32_t sb = smem_u32(smem);
    const int tid  = threadIdx.x;
    const int wid  = tid >> 5;
    const int lane = tid & 31;
    const int ntile = blockIdx.x;     // 0..31
    const int mtile = blockIdx.y;     // 0..63

    const int warpM = wid >> 1;       // 0..3 -> m offset warpM*32
    const int warpN = wid & 1;        // 0..1 -> n offset warpN*64

    if (tid == 0) {
#pragma unroll
        for (int s = 0; s < NSTAGES; ++s) MBAR_INIT(sb + OFF_FULL(s), 1);
    }
    __syncthreads();

    const unsigned char* gA = g_A  + ((size_t)mtile * KT) * A_TILE_BYTES;
    const unsigned char* gW = g_Wt + ((size_t)ntile * KT) * W_TILE_BYTES;

    // prefill all stages
    if (tid == 0) {
#pragma unroll
        for (int it = 0; it < NSTAGES; ++it) {
            uint32_t full = sb + OFF_FULL(it);
            MBAR_EXPECT_TX(full, STAGE_BYTES);
            uint32_t base = sb + STAGE_BASE(it);
            bulk_g2s(base + ST_A, gA + (size_t)it * A_TILE_BYTES, A_TILE_BYTES, full);
            bulk_g2s(base + ST_W, gW + (size_t)it * W_TILE_BYTES, W_TILE_BYTES, full);
        }
    }

    float acc[2][8][4];               // [mf 16-row][n8 block][frag]
#pragma unroll
    for (int i = 0; i < 2; ++i)
#pragma unroll
        for (int j = 0; j < 8; ++j)
#pragma unroll
            for (int q = 0; q < 4; ++q) acc[i][j][q] = 0.f;

    // Precompute ALL LDSM within-stage offsets (swizzle XOR hoisted):
    // offA[mf][ks] = ST_A + r*128 + ((c2 ^ ((r&7)<<4)))  for r = warpM*32+mf*16+lr
    const int lr = lane & 15;
    const int lc = (lane >> 4) << 3;
    uint32_t offA[2][4], offW[4][4];
#pragma unroll
    for (int mf = 0; mf < 2; ++mf) {
        int r = warpM * 32 + mf * 16 + lr;
        uint32_t key = (uint32_t)((r & 7) << 4);
#pragma unroll
        for (int ks = 0; ks < 4; ++ks) {
            uint32_t c2 = (uint32_t)((ks * 16 + lc) * 2);
            offA[mf][ks] = (uint32_t)(ST_A + r * 128) + (c2 ^ key);
        }
    }
#pragma unroll
    for (int nf = 0; nf < 4; ++nf) {
        int r = warpN * 64 + nf * 16 + lr;
        uint32_t key = (uint32_t)((r & 7) << 4);
#pragma unroll
        for (int ks = 0; ks < 4; ++ks) {
            uint32_t c2 = (uint32_t)((ks * 16 + lc) * 2);
            offW[nf][ks] = (uint32_t)(ST_W + r * 128) + (c2 ^ key);
        }
    }

    uint32_t af[2][4], bw[4][4];   // single-buffered fragments

    // One pipeline body for compile-time stage S at iteration IT, parity PH.
#define BODY(S, IT, PH)                                                        \
    do {                                                                       \
        MBAR_WAIT(sb + OFF_FULL(S), (PH));                                     \
        _Pragma("unroll")                                                      \
        for (int ks = 0; ks < 4; ++ks) {                                       \
            _Pragma("unroll")                                                  \
            for (int mf = 0; mf < 2; ++mf)                                     \
                ldsm4(af[mf], sb + (uint32_t)STAGE_BASE(S) + offA[mf][ks]);    \
            _Pragma("unroll")                                                  \
            for (int nf = 0; nf < 4; ++nf)                                     \
                ldsm4(bw[nf], sb + (uint32_t)STAGE_BASE(S) + offW[nf][ks]);    \
            _Pragma("unroll")                                                  \
            for (int mf = 0; mf < 2; ++mf) {                                   \
                _Pragma("unroll")                                              \
                for (int nf = 0; nf < 4; ++nf) {                               \
                    mma_fp16(acc[mf][2 * nf + 0], af[mf], bw[nf][0], bw[nf][2]); \
                    mma_fp16(acc[mf][2 * nf + 1], af[mf], bw[nf][1], bw[nf][3]); \
                }                                                              \
            }                                                                  \
        }                                                                      \
        if (wid == 0) {                                                        \
            BAR_SYNC(1 + (S));                                                 \
            if (tid == 0 && (IT) + NSTAGES < KT) {                             \
                int nit = (IT) + NSTAGES;                                      \
                uint32_t full = sb + OFF_FULL(S);                              \
                MBAR_EXPECT_TX(full, STAGE_BYTES);                             \
                uint32_t nb = sb + (uint32_t)STAGE_BASE(S);                    \
                bulk_g2s(nb + ST_A, gA + (size_t)nit * A_TILE_BYTES, A_TILE_BYTES, full); \
                bulk_g2s(nb + ST_W, gW + (size_t)nit * W_TILE_BYTES, W_TILE_BYTES, full); \
            }                                                                  \
        } else {                                                               \
            BAR_ARRIVE(1 + (S));                                               \
        }                                                                      \
    } while (0)

    // 64 iterations = 21 groups of 3 (stage = it mod 3, parity = group&1) + 1.
#pragma unroll 1
    for (int g = 0; g < 21; ++g) {
        const int ph  = g & 1;
        const int it0 = 3 * g;
        BODY(0, it0 + 0, ph);
        BODY(1, it0 + 1, ph);
        BODY(2, it0 + 2, ph);
    }
    BODY(0, 63, 1);   // 22nd use of stage 0: parity floor(63/3)&1 = 1
#undef BODY

    // -------- epilogue: registers -> gmem (sector-complete float2 stores) ----
    const int tq = lane >> 2;   // 0..7 row within 8
    const int tr = lane & 3;    // col pair
    const int m_base = mtile * BM + warpM * 32;
    const int n_base = ntile * BN + warpN * 64;

#pragma unroll
    for (int mf = 0; mf < 2; ++mf) {
        int r0 = m_base + mf * 16 + tq;
        int r1 = r0 + 8;
        float rs0 = g_rowsum[r0];
        float rs1 = g_rowsum[r1];
        float* o0 = out + (size_t)r0 * DIM_N;
        float* o1 = out + (size_t)r1 * DIM_N;
#pragma unroll
        for (int j = 0; j < 8; ++j) {
            int n = n_base + j * 8 + 2 * tr;
            float2 sc = *reinterpret_cast<const float2*>(scale + n);
            float2 zq = *reinterpret_cast<const float2*>(zp + n);
            float2 bb = *reinterpret_cast<const float2*>(bias + n);
            float* c = acc[mf][j];
            float2 v0, v1;
            v0.x = c[0] * sc.x + bb.x - sc.x * zq.x * rs0;
            v0.y = c[1] * sc.y + bb.y - sc.y * zq.y * rs0;
            v1.x = c[2] * sc.x + bb.x - sc.x * zq.x * rs1;
            v1.y = c[3] * sc.y + bb.y - sc.y * zq.y * rs1;
            *reinterpret_cast<float2*>(o0 + n) = v0;
            *reinterpret_cast<float2*>(o1 + n) = v1;
        }
    }
}

// ---------------- launch ----------------
extern "C" void kernel_launch(void* const* d_in, const int* in_sizes, int n_in,
                              void* d_out, int out_size) {
    const float* input  = (const float*)d_in[0];   // [4,2048,4096] fp32
    const int*   w_int  = (const int*)  d_in[1];   // [4096,4096] int32
    const float* scale  = (const float*)d_in[2];   // [4096,1]
    const float* zp     = (const float*)d_in[3];   // [4096,1]
    const float* bias   = (const float*)d_in[4];   // [4096]
    float* out = (float*)d_out;

    k_convert<<<DIM_N + DIM_M, 512>>>(w_int, input);

    cudaFuncSetAttribute(k_gemm, cudaFuncAttributeMaxDynamicSharedMemorySize, SMEM_DYN);

    dim3 grid(NT, MT);   // x = n-tile fastest: co-resident CTAs share A tiles in L2
    k_gemm<<<grid, 256, SMEM_DYN>>>(scale, zp, bias, out);
}